// round 1
// baseline (speedup 1.0000x reference)
#include <cuda_runtime.h>

#define BB 64
#define PP 8732
#define CC 81
#define OO 32

// ---------------- scratch (static device globals; no allocation) ----------------
__device__ float g_ov[BB*PP];
__device__ int   g_oi[BB*PP];
__device__ int   g_lab[BB*PP];
__device__ float g_ce[BB*PP];
__device__ unsigned long long g_bestkey[BB*OO];
__device__ float g_loc_sum;
__device__ int   g_npos;
__device__ float g_cepos;
__device__ float g_hard;

// ---------------- helpers ----------------
__device__ __forceinline__ unsigned order_key(float f) {
    unsigned u = __float_as_uint(f);
    return (u & 0x80000000u) ? ~u : (u | 0x80000000u);
}
__device__ __forceinline__ float key_val(unsigned u) {
    u = (u & 0x80000000u) ? (u & 0x7FFFFFFFu) : ~u;
    return __uint_as_float(u);
}

// ---------------- k0: zero accumulators ----------------
__global__ void k0_init() {
    int t = blockIdx.x * blockDim.x + threadIdx.x;
    if (t < BB*OO) g_bestkey[t] = 0ULL;
    if (t == 0) { g_loc_sum = 0.f; g_npos = 0; g_cepos = 0.f; g_hard = 0.f; }
}

// ---------------- k1: IoU matching ----------------
// grid: (ceil(P/256), B), 256 threads. One prior per thread.
__global__ void k1_match(const float* __restrict__ tb, const float* __restrict__ pbx) {
    int b = blockIdx.y;
    int p = blockIdx.x * 256 + threadIdx.x;
    __shared__ float sx0[OO], sy0[OO], sx1[OO], sy1[OO], sarea[OO];
    __shared__ unsigned long long sbest[OO];
    if (threadIdx.x < OO) {
        const float* t4 = tb + (size_t)(b*OO + threadIdx.x) * 4;
        float x0 = t4[0], y0 = t4[1], x1 = t4[2], y1 = t4[3];
        sx0[threadIdx.x] = x0; sy0[threadIdx.x] = y0;
        sx1[threadIdx.x] = x1; sy1[threadIdx.x] = y1;
        sarea[threadIdx.x] = (x1 - x0) * (y1 - y0);
        sbest[threadIdx.x] = 0ULL;
    }
    __syncthreads();

    bool valid = (p < PP);
    float bx0 = 0, by0 = 0, bx1 = 0, by1 = 0, areab = 0;
    if (valid) {
        const float* pr = pbx + (size_t)p * 4;
        float cx = pr[0], cy = pr[1], w = pr[2], h = pr[3];
        bx0 = cx - 0.5f * w; bx1 = cx + 0.5f * w;
        by0 = cy - 0.5f * h; by1 = cy + 0.5f * h;
        areab = w * h;
    }
    float bestv = -1.f; int besti = 0;
    int lane = threadIdx.x & 31;
    #pragma unroll 4
    for (int o = 0; o < OO; o++) {
        unsigned long long key = 0ULL;
        if (valid) {
            float lx = fmaxf(sx0[o], bx0), ly = fmaxf(sy0[o], by0);
            float rx = fminf(sx1[o], bx1), ry = fminf(sy1[o], by1);
            float iw = fmaxf(rx - lx, 0.f), ih = fmaxf(ry - ly, 0.f);
            float inter = iw * ih;
            float uni = sarea[o] + areab - inter;
            float iou = __fdividef(inter, uni);           // iou >= 0 always
            if (iou > bestv) { bestv = iou; besti = o; }  // first-index tiebreak
            key = ((unsigned long long)(__float_as_uint(iou) | 0x80000000u) << 32)
                | (unsigned long long)(0xFFFFFFFFu - (unsigned)p); // smaller p wins ties
        }
        // warp reduce max key
        #pragma unroll
        for (int off = 16; off; off >>= 1) {
            unsigned long long o2 = __shfl_down_sync(0xffffffffu, key, off);
            if (o2 > key) key = o2;
        }
        if (lane == 0) atomicMax(&sbest[o], key);
    }
    __syncthreads();
    if (threadIdx.x < OO) atomicMax(&g_bestkey[b*OO + threadIdx.x], sbest[threadIdx.x]);
    if (valid) { g_ov[b*PP + p] = bestv; g_oi[b*PP + p] = besti; }
}

// ---------------- k2: sequential scatter (last write wins, per batch) ----------------
__global__ void k2_scatter() {
    int b = threadIdx.x;
    if (b < BB) {
        for (int o = 0; o < OO; o++) {
            unsigned long long key = g_bestkey[b*OO + o];
            unsigned p = 0xFFFFFFFFu - (unsigned)(key & 0xFFFFFFFFull);
            g_oi[b*PP + p] = o;
            g_ov[b*PP + p] = 1.0f;
        }
    }
}

// ---------------- k3: labels + localization loss partials ----------------
__global__ void k3_labels(const float* __restrict__ pred, const float* __restrict__ tb,
                          const int* __restrict__ tc, const float* __restrict__ pbx) {
    int b = blockIdx.y;
    int p = blockIdx.x * 256 + threadIdx.x;
    float l1 = 0.f; int cnt = 0;
    if (p < PP) {
        int idx = b*PP + p;
        float ov = g_ov[idx]; int oi = g_oi[idx];
        int lab = (ov < 0.5f) ? 0 : tc[b*OO + oi];
        g_lab[idx] = lab;
        if (lab != 0) {
            const float* t4 = tb + (size_t)(b*OO + oi) * 4;
            float x0 = t4[0], y0 = t4[1], x1 = t4[2], y1 = t4[3];
            const float* pr = pbx + (size_t)p * 4;
            float pcx = pr[0], pcy = pr[1], pw = pr[2], ph = pr[3];
            float gcx = ((x0 + x1) * 0.5f - pcx) * 10.f / pw;
            float gcy = ((y0 + y1) * 0.5f - pcy) * 10.f / ph;
            float gw  = logf((x1 - x0) / pw) * 5.f;
            float gh  = logf((y1 - y0) / ph) * 5.f;
            const float* pd = pred + (size_t)idx * 4;
            l1 = fabsf(pd[0]-gcx) + fabsf(pd[1]-gcy) + fabsf(pd[2]-gw) + fabsf(pd[3]-gh);
            cnt = 1;
        }
    }
    int lane = threadIdx.x & 31;
    #pragma unroll
    for (int off = 16; off; off >>= 1) {
        l1  += __shfl_xor_sync(0xffffffffu, l1, off);
        cnt += __shfl_xor_sync(0xffffffffu, cnt, off);
    }
    __shared__ float sl[8]; __shared__ int sc[8];
    if (lane == 0) { sl[threadIdx.x >> 5] = l1; sc[threadIdx.x >> 5] = cnt; }
    __syncthreads();
    if (threadIdx.x == 0) {
        float a = 0.f; int c = 0;
        #pragma unroll
        for (int i = 0; i < 8; i++) { a += sl[i]; c += sc[i]; }
        if (a != 0.f) atomicAdd(&g_loc_sum, a);
        if (c) atomicAdd(&g_npos, c);
    }
}

// ---------------- k4: per-prior cross-entropy (warp per prior) ----------------
__global__ void k4_ce(const float* __restrict__ scores) {
    int lane = threadIdx.x & 31;
    int warp = (blockIdx.x * blockDim.x + threadIdx.x) >> 5;
    int nwarps = (gridDim.x * blockDim.x) >> 5;
    float acc = 0.f;
    for (int idx = warp; idx < BB*PP; idx += nwarps) {
        const float* s = scores + (size_t)idx * CC;
        float s0 = s[lane];
        float s1 = s[lane + 32];
        float s2 = (lane < CC - 64) ? s[lane + 64] : -3.4e38f;
        float m = fmaxf(fmaxf(s0, s1), s2);
        #pragma unroll
        for (int off = 16; off; off >>= 1) m = fmaxf(m, __shfl_xor_sync(0xffffffffu, m, off));
        float e = __expf(s0 - m) + __expf(s1 - m) + ((lane < CC - 64) ? __expf(s2 - m) : 0.f);
        #pragma unroll
        for (int off = 16; off; off >>= 1) e += __shfl_xor_sync(0xffffffffu, e, off);
        float lse = m + __logf(e);
        int lab = g_lab[idx];
        float sl;
        if (lab < 32)      sl = __shfl_sync(0xffffffffu, s0, lab);
        else if (lab < 64) sl = __shfl_sync(0xffffffffu, s1, lab - 32);
        else               sl = __shfl_sync(0xffffffffu, s2, lab - 64);
        float ce = lse - sl;
        if (lane == 0) {
            g_ce[idx] = ce;
            if (lab != 0) acc += ce;
        }
    }
    // block reduce acc (only lane0 of each warp holds a nonzero value)
    #pragma unroll
    for (int off = 16; off; off >>= 1) acc += __shfl_xor_sync(0xffffffffu, acc, off);
    __shared__ float sw[32];
    if (lane == 0) sw[threadIdx.x >> 5] = acc;
    __syncthreads();
    if (threadIdx.x == 0) {
        float t = 0.f;
        int nw = blockDim.x >> 5;
        for (int i = 0; i < nw; i++) t += sw[i];
        if (t != 0.f) atomicAdd(&g_cepos, t);
    }
}

// ---------------- k5: per-row top-k sum via exact radix select ----------------
// one block per row (B rows), 512 threads. k = min(3*n_pos, P).
__global__ void k5_select() {
    __shared__ unsigned skeys[PP];
    __shared__ int bins[256];
    __shared__ unsigned sh_pref;
    __shared__ int sh_rem;
    __shared__ float swsum[16];
    __shared__ int swcnt[16];
    int r = blockIdx.x;
    int tid = threadIdx.x, bd = blockDim.x;
    for (int p = tid; p < PP; p += bd) skeys[p] = order_key(g_ce[(size_t)r*PP + p]);
    __syncthreads();
    long long k = 3LL * (long long)g_npos;
    if (k <= 0) return;
    int lane = tid & 31, wid = tid >> 5;

    if (k >= PP) {
        // sum the whole row
        float s = 0.f;
        for (int p = tid; p < PP; p += bd) s += key_val(skeys[p]);
        #pragma unroll
        for (int off = 16; off; off >>= 1) s += __shfl_xor_sync(0xffffffffu, s, off);
        if (lane == 0) swsum[wid] = s;
        __syncthreads();
        if (tid == 0) {
            float t = 0.f;
            for (int i = 0; i < (bd >> 5); i++) t += swsum[i];
            atomicAdd(&g_hard, t);
        }
        return;
    }

    unsigned prefix = 0; int rem = (int)k;
    for (int shift = 24; shift >= 0; shift -= 8) {
        if (tid < 256) bins[tid] = 0;
        __syncthreads();
        unsigned hi_mask = (shift == 24) ? 0u : (0xFFFFFFFFu << (shift + 8));
        for (int p = tid; p < PP; p += bd) {
            unsigned key = skeys[p];
            if ((key & hi_mask) == prefix) atomicAdd(&bins[(key >> shift) & 255], 1);
        }
        __syncthreads();
        if (tid == 0) {
            int cum = 0;
            for (int bi = 255; bi >= 0; bi--) {
                int c = bins[bi];
                if (cum + c >= rem) { sh_rem = rem - cum; sh_pref = prefix | ((unsigned)bi << shift); break; }
                cum += c;
            }
        }
        __syncthreads();
        prefix = sh_pref; rem = sh_rem;
        __syncthreads();
    }
    unsigned kth = prefix;  // exact k-th largest key
    float sumv = 0.f; int cgt = 0;
    for (int p = tid; p < PP; p += bd) {
        unsigned key = skeys[p];
        if (key > kth) { sumv += key_val(key); cgt++; }
    }
    #pragma unroll
    for (int off = 16; off; off >>= 1) {
        sumv += __shfl_xor_sync(0xffffffffu, sumv, off);
        cgt  += __shfl_xor_sync(0xffffffffu, cgt, off);
    }
    if (lane == 0) { swsum[wid] = sumv; swcnt[wid] = cgt; }
    __syncthreads();
    if (tid == 0) {
        float t = 0.f; int c = 0;
        for (int i = 0; i < (bd >> 5); i++) { t += swsum[i]; c += swcnt[i]; }
        float total = t + (float)(k - c) * key_val(kth);  // handles ties exactly
        atomicAdd(&g_hard, total);
    }
}

// ---------------- k6: finalize ----------------
__global__ void k6_final(float* __restrict__ out) {
    float np = (float)g_npos;
    out[0] = g_loc_sum / (np * 4.f) + (g_cepos + g_hard) / np;
}

// ---------------- launch ----------------
extern "C" void kernel_launch(void* const* d_in, const int* in_sizes, int n_in,
                              void* d_out, int out_size) {
    const float* pred_boxes   = (const float*)d_in[0];
    const float* pred_scores  = (const float*)d_in[1];
    const float* true_boxes   = (const float*)d_in[2];
    const int*   true_classes = (const int*)d_in[3];
    const float* pboxes       = (const float*)d_in[4];
    float* out = (float*)d_out;
    (void)in_sizes; (void)n_in; (void)out_size;

    k0_init<<<2, 1024>>>();
    dim3 g1((PP + 255) / 256, BB);
    k1_match<<<g1, 256>>>(true_boxes, pboxes);
    k2_scatter<<<1, 64>>>();
    k3_labels<<<g1, 256>>>(pred_boxes, true_boxes, true_classes, pboxes);
    k4_ce<<<2048, 256>>>(pred_scores);
    k5_select<<<BB, 512>>>();
    k6_final<<<1, 1>>>(out);
}